// round 16
// baseline (speedup 1.0000x reference)
#include <cuda_runtime.h>
#include <cuda_bf16.h>
#include <cstdint>

// ---------------------------------------------------------------------------
// ProtoTSNet on GB300 — round 16
//  - gemm: 4 t-tiles per CTA (grid 8xBx3) — proto prologue amortized 4x
//  - enc: w1 staged via cp.async into smem scratch, split from smem
//
// out[0..319]    = logits [32,10]
// out[320..6719] = min_distances [32,200]
// ---------------------------------------------------------------------------

#define B_     32
#define FIN    16
#define L_     8192
#define LAT    64
#define L1_    8190
#define P_     200
#define KP     16
#define LO     8175
#define C_     10
#define EPS_   1e-4f
#define TPAD   8224

// ---------------- static device scratch (allocation-free) -----------------
__device__ __nv_bfloat16 d_fT[B_ * TPAD * LAT];    // f [b][t][c], bf16
__device__ __nv_bfloat16 d_protA[16 * 256 * LAT];  // protos [kk][p pad256][c]
__device__ float         d_p2[256];                // ||p||^2 (bf16-rounded)

__device__ __forceinline__ uint32_t smem_u32(const void* p) {
    uint32_t a;
    asm("{ .reg .u64 t; cvta.to.shared.u64 t, %1; cvt.u32.u64 %0, t; }"
        : "=r"(a) : "l"(p));
    return a;
}
__device__ __forceinline__ void cp16(uint32_t s, const void* g) {
    asm volatile("cp.async.cg.shared.global [%0], [%1], 16;" :: "r"(s), "l"(g));
}
#define CP_COMMIT() asm volatile("cp.async.commit_group;" ::: "memory")
#define CP_WAIT0()  asm volatile("cp.async.wait_group 0;" ::: "memory")

__device__ __forceinline__ void mma16816(float* c, const uint32_t* a,
                                         const uint32_t* b)
{
    asm volatile(
        "mma.sync.aligned.m16n8k16.row.col.f32.bf16.bf16.f32 "
        "{%0,%1,%2,%3}, {%4,%5,%6,%7}, {%8,%9}, {%0,%1,%2,%3};"
        : "+f"(c[0]), "+f"(c[1]), "+f"(c[2]), "+f"(c[3])
        : "r"(a[0]), "r"(a[1]), "r"(a[2]), "r"(a[3]), "r"(b[0]), "r"(b[1]));
}
#define LDSM4(r0, r1, r2, r3, addr)                                           \
    asm volatile("ldmatrix.sync.aligned.m8n8.x4.shared.b16 {%0,%1,%2,%3},[%4];" \
        : "=r"(r0), "=r"(r1), "=r"(r2), "=r"(r3) : "r"(addr))

__device__ __forceinline__ uint32_t pack_bf2(__nv_bfloat16 a, __nv_bfloat16 b)
{
    return (uint32_t)__bfloat16_as_ushort(a)
         | ((uint32_t)__bfloat16_as_ushort(b) << 16);
}

// ---------------------------------------------------------------------------
// Kernel A: enc (grid.x < 64) + prep (grid.x >= 64), block-range dispatch
// ---------------------------------------------------------------------------
#define B1_ROWB 80
#define OFF_B1  0                       // x tile  [130][80B] (16hi|16lo)
#define OFF_A1  10560                   // w1      [3][64][80B]
#define OFF_A2  25920                   // w2      [64][272B]
#define OFF_B2  43328                   // f1 tile [128][272B]; w1 staging early
#define ENC_DYN 78144
#define ENC_XBLKS 64
#define PREP_XBLKS 40                   // 40*32 = 1280 >= 1249 prep blocks

__device__ void prep_body(int blk, const float* __restrict__ protos,
                          unsigned* __restrict__ md)
{
    const int tid = threadIdx.x;
    if (blk < 1024) {                              // protA rearrange
        int idx = blk * 256 + tid;
        int c  = idx & 63;
        int pp = (idx >> 6) & 255;
        int kk = idx >> 14;
        float v = (pp < P_) ? protos[pp * (LAT * KP) + c * KP + kk] : 0.f;
        d_protA[idx] = __float2bfloat16(v);
    } else if (blk < 1224) {                       // p2
        const int p = blk - 1024;
        float s = 0.f;
        for (int i = tid; i < LAT * KP; i += 256) {
            float v = __bfloat162float(__float2bfloat16(protos[p * LAT * KP + i]));
            s += v * v;
        }
#pragma unroll
        for (int o = 16; o; o >>= 1) s += __shfl_xor_sync(0xffffffffu, s, o);
        __shared__ float red[8];
        if ((tid & 31) == 0) red[tid >> 5] = s;
        __syncthreads();
        if (tid == 0) {
            float ts = 0.f;
            for (int w = 0; w < 8; w++) ts += red[w];
            d_p2[p] = ts;
        }
    } else if (blk < 1249) {                       // init md
        int i = (blk - 1224) * 256 + tid;
        if (i < B_ * P_) md[i] = 0x7f800000u;
    }
}

__global__ void __launch_bounds__(256, 2)
enc_prep_kernel(const float* __restrict__ x,
                const float* __restrict__ ew,
                const float* __restrict__ aw,
                const float* __restrict__ protos,
                unsigned* __restrict__ md)
{
    if (blockIdx.x >= ENC_XBLKS) {
        prep_body((blockIdx.x - ENC_XBLKS) * B_ + blockIdx.y, protos, md);
        return;
    }

    extern __shared__ char esm[];

    const int b   = blockIdx.y;
    const int t0  = blockIdx.x * 128;
    const int tid = threadIdx.x;
    const int lane = tid & 31;
    const int wid  = tid >> 5;
    const int wm  = wid & 3;
    const int wn  = wid >> 2;
    const int sub = lane >> 3;
    const int lr  = lane & 7;
    const int g   = lane >> 2;
    const int tig = lane & 3;

    const uint32_t b1_u = smem_u32(esm) + OFF_B1;
    const uint32_t a1_u = smem_u32(esm) + OFF_A1;
    const uint32_t a2_u = smem_u32(esm) + OFF_A2;
    const uint32_t b2_u = smem_u32(esm) + OFF_B2;

    // ---- stage raw w1 (3072 floats) into B2 scratch via cp.async ----
    for (int i = tid; i < 768; i += 256)
        cp16(b2_u + i * 16, ew + i * 4);
    CP_COMMIT();

    // ---- x tile: load + split hi/lo, packed u32 stores ----
    for (int idx = tid; idx < 8 * 130; idx += 256) {
        int i2 = idx / 130, r = idx - i2 * 130;
        int t = t0 + r;
        int i = i2 * 2;
        float v0 = (t < L_) ? x[(b * FIN + i)     * L_ + t] : 0.f;
        float v1 = (t < L_) ? x[(b * FIN + i + 1) * L_ + t] : 0.f;
        __nv_bfloat16 h0 = __float2bfloat16(v0);
        __nv_bfloat16 h1 = __float2bfloat16(v1);
        __nv_bfloat16 l0 = __float2bfloat16(v0 - __bfloat162float(h0));
        __nv_bfloat16 l1 = __float2bfloat16(v1 - __bfloat162float(h1));
        char* row = esm + OFF_B1 + r * B1_ROWB;
        *reinterpret_cast<uint32_t*>(row + i2 * 4)      = pack_bf2(h0, h1);
        *reinterpret_cast<uint32_t*>(row + 32 + i2 * 4) = pack_bf2(l0, l1);
    }
    // ---- w2: split on the fly (coalesced global), packed ----
    for (int idx = tid; idx < 64 * 32; idx += 256) {
        int c2 = idx & 31, ch2 = idx >> 5;
        float w0 = aw[ch2 * 64 + c2 * 2];
        float w1 = aw[ch2 * 64 + c2 * 2 + 1];
        __nv_bfloat16 h0 = __float2bfloat16(w0);
        __nv_bfloat16 h1 = __float2bfloat16(w1);
        __nv_bfloat16 l0 = __float2bfloat16(w0 - __bfloat162float(h0));
        __nv_bfloat16 l1 = __float2bfloat16(w1 - __bfloat162float(h1));
        char* row = esm + OFF_A2 + ch2 * 272;
        *reinterpret_cast<uint32_t*>(row + c2 * 4)       = pack_bf2(h0, h1);
        *reinterpret_cast<uint32_t*>(row + 128 + c2 * 4) = pack_bf2(l0, l1);
    }
    // ---- w1: split from smem staging ----
    CP_WAIT0();
    __syncthreads();
    const float* ws = reinterpret_cast<const float*>(esm + OFF_B2);
    for (int idx = tid; idx < 3 * 64 * 8; idx += 256) {
        int i2 = idx & 7, ch = (idx >> 3) & 63, tap = idx >> 9;
        int i = i2 * 2;
        float w0 = ws[ch * 48 + i * 3 + tap];
        float w1 = ws[ch * 48 + (i + 1) * 3 + tap];
        __nv_bfloat16 h0 = __float2bfloat16(w0);
        __nv_bfloat16 h1 = __float2bfloat16(w1);
        __nv_bfloat16 l0 = __float2bfloat16(w0 - __bfloat162float(h0));
        __nv_bfloat16 l1 = __float2bfloat16(w1 - __bfloat162float(h1));
        char* row = esm + OFF_A1 + tap * (64 * B1_ROWB) + ch * B1_ROWB;
        *reinterpret_cast<uint32_t*>(row + i2 * 4)      = pack_bf2(h0, h1);
        *reinterpret_cast<uint32_t*>(row + 32 + i2 * 4) = pack_bf2(l0, l1);
    }
    __syncthreads();

    // ---- stage 1: conv k=3 ----
    float acc1[2][4][4];
#pragma unroll
    for (int mt = 0; mt < 2; mt++)
#pragma unroll
        for (int nt = 0; nt < 4; nt++)
#pragma unroll
            for (int e = 0; e < 4; e++) acc1[mt][nt][e] = 0.f;

    const uint32_t a1row  = (uint32_t)(wm * 32 + (sub & 1) * 8 + lr);
    const uint32_t a1colq = (uint32_t)((sub >> 1) * 16);
    const uint32_t w1row  = (uint32_t)((wn * 32 + (sub >> 1) * 8 + lr) * B1_ROWB
                                       + (sub & 1) * 16);

#pragma unroll
    for (int tap = 0; tap < 3; tap++) {
#pragma unroll
        for (int pass = 0; pass < 3; pass++) {
            const uint32_t colA = (pass == 2) ? 32u : 0u;
            const uint32_t colB = (pass == 1) ? 32u : 0u;
            uint32_t bf[4][2];
            const uint32_t wb = a1_u + tap * (64 * B1_ROWB) + w1row + colB;
            LDSM4(bf[0][0], bf[0][1], bf[1][0], bf[1][1], wb);
            LDSM4(bf[2][0], bf[2][1], bf[3][0], bf[3][1], wb + 16 * B1_ROWB);
#pragma unroll
            for (int mt = 0; mt < 2; mt++) {
                uint32_t a[4];
                LDSM4(a[0], a[1], a[2], a[3],
                      b1_u + (a1row + mt * 16 + tap) * B1_ROWB + a1colq + colA);
#pragma unroll
                for (int nt = 0; nt < 4; nt++)
                    mma16816(acc1[mt][nt], a, bf[nt]);
            }
        }
    }
    __syncthreads();   // B2 staging fully consumed before f1 overwrites it

    // ---- epilogue 1 ----
#pragma unroll
    for (int mt = 0; mt < 2; mt++) {
#pragma unroll
        for (int nt = 0; nt < 4; nt++) {
#pragma unroll
            for (int eh = 0; eh < 2; eh++) {
                const int t  = wm * 32 + mt * 16 + g + eh * 8;
                const int ch = wn * 32 + nt * 8 + tig * 2;
                float v0 = fmaxf(acc1[mt][nt][eh * 2 + 0], 0.f);
                float v1 = fmaxf(acc1[mt][nt][eh * 2 + 1], 0.f);
                __nv_bfloat16 h0 = __float2bfloat16(v0);
                __nv_bfloat16 h1 = __float2bfloat16(v1);
                __nv_bfloat16 l0 = __float2bfloat16(v0 - __bfloat162float(h0));
                __nv_bfloat16 l1 = __float2bfloat16(v1 - __bfloat162float(h1));
                char* row = esm + OFF_B2 + t * 272;
                *reinterpret_cast<uint32_t*>(row + ch * 2)       = pack_bf2(h0, h1);
                *reinterpret_cast<uint32_t*>(row + 128 + ch * 2) = pack_bf2(l0, l1);
            }
        }
    }
    __syncthreads();

    // ---- stage 2: 1x1 addon ----
    float acc2[2][4][4];
#pragma unroll
    for (int mt = 0; mt < 2; mt++)
#pragma unroll
        for (int nt = 0; nt < 4; nt++)
#pragma unroll
            for (int e = 0; e < 4; e++) acc2[mt][nt][e] = 0.f;

    const uint32_t a2base = b2_u + (uint32_t)((wm * 32 + (sub & 1) * 8 + lr) * 272
                                              + (sub >> 1) * 16);
    const uint32_t w2base = a2_u + (uint32_t)((wn * 32 + (sub >> 1) * 8 + lr) * 272
                                              + (sub & 1) * 16);

#pragma unroll
    for (int step = 0; step < 12; step++) {
        const int kc   = step & 3;
        const int pass = step >> 2;
        const uint32_t colA = (pass == 2) ? (128u + kc * 32u) : (kc * 32u);
        const uint32_t colB = (pass == 1) ? (128u + kc * 32u) : (kc * 32u);
        uint32_t bf[4][2];
        LDSM4(bf[0][0], bf[0][1], bf[1][0], bf[1][1], w2base + colB);
        LDSM4(bf[2][0], bf[2][1], bf[3][0], bf[3][1], w2base + colB + 16 * 272);
#pragma unroll
        for (int mt = 0; mt < 2; mt++) {
            uint32_t a[4];
            LDSM4(a[0], a[1], a[2], a[3], a2base + mt * (16 * 272) + colA);
#pragma unroll
            for (int nt = 0; nt < 4; nt++)
                mma16816(acc2[mt][nt], a, bf[nt]);
        }
    }

    // ---- epilogue 2: relu, round bf16, store f ----
#pragma unroll
    for (int mt = 0; mt < 2; mt++) {
#pragma unroll
        for (int eh = 0; eh < 2; eh++) {
            const int tg = t0 + wm * 32 + mt * 16 + g + eh * 8;
            if (tg < L1_) {
#pragma unroll
                for (int nt = 0; nt < 4; nt++) {
                    const int ch = wn * 32 + nt * 8 + tig * 2;
                    float v0 = fmaxf(acc2[mt][nt][eh * 2 + 0], 0.f);
                    float v1 = fmaxf(acc2[mt][nt][eh * 2 + 1], 0.f);
                    __nv_bfloat162 h2 = __floats2bfloat162_rn(v0, v1);
                    *reinterpret_cast<uint32_t*>(
                        d_fT + ((size_t)b * TPAD + tg) * LAT + ch) =
                        *reinterpret_cast<uint32_t*>(&h2);
                }
            }
        }
    }
}

// ---------------------------------------------------------------------------
// Kernel B: HMMA GEMM + distance + min-reduce
//   grid (8, B, 3): z chunks 80/80/48 rows, ALL 16 taps resident,
//   4 t-tiles of 256 per CTA. s_g computed in-kernel from the f tile.
// ---------------------------------------------------------------------------
#define NT_       256
#define FROWS     272
#define ROWB      144
#define SF_BYTES  (FROWS * ROWB)               // 39168
#define GEMM_DYN  (SF_BYTES + 16 * 80 * ROWB)  // 223488

template<int MBW, int P0>
__device__ __forceinline__ void gemm_body(unsigned* __restrict__ md,
                                          char* dynsm, float* s_g, float* s2s,
                                          float* s_p2, unsigned* s_md)
{
    constexpr int MB16 = MBW * 16;
    constexpr int SP_TAPB = MB16 * ROWB;

    char* sf = dynsm;
    char* sp = dynsm + SF_BYTES;

    const int b   = blockIdx.y;
    const int tid = threadIdx.x;
    const int lane = tid & 31;
    const int wid  = tid >> 5;
    const int sub = lane >> 3;
    const int lr  = lane & 7;
    const int g   = lane >> 2;
    const int tig = lane & 3;

    const uint32_t sf_u32 = smem_u32(sf);
    const uint32_t sp_u32 = smem_u32(sp);

    // ---- protos: all 16 taps, loaded once ----
    for (int i = tid; i < 16 * MB16 * 8; i += 256) {
        int j = i / (MB16 * 8), rs = i % (MB16 * 8);
        int r = rs >> 3, seg = rs & 7;
        cp16(sp_u32 + j * SP_TAPB + r * ROWB + seg * 16,
             d_protA + ((size_t)(j * 256 + P0 + r)) * LAT + seg * 8);
    }
    if (tid < 128) {
        s_p2[tid] = d_p2[P0 + tid];
        s_md[tid] = 0x7f800000u;
    }

    const __nv_bfloat16* fT = d_fT + (size_t)b * TPAD * LAT;
    const uint32_t a_off = (uint32_t)(((sub & 1) * 8 + lr) * ROWB
                                      + (sub >> 1) * 16);
    const uint32_t b_off = (uint32_t)((wid * 32 + (sub >> 1) * 8 + lr) * ROWB
                                      + (sub & 1) * 16);

#pragma unroll 1
    for (int it = 0; it < 4; it++) {
        const int t0 = (blockIdx.x * 4 + it) * NT_;

        // f tile for this t-tile (protos stay resident)
        for (int i = tid; i < FROWS * 8; i += 256) {
            int r = i >> 3, seg = i & 7;
            cp16(sf_u32 + r * ROWB + seg * 16,
                 fT + (size_t)(t0 + r) * LAT + seg * 8);
        }
        CP_COMMIT();
        CP_WAIT0();
        __syncthreads();

        // s_g[r] = sum_c f[r][c]^2 from the resident f tile
        for (int r = tid; r < FROWS; r += 256) {
            const uint32_t* row = reinterpret_cast<const uint32_t*>(sf + r * ROWB);
            float s = 0.f;
#pragma unroll
            for (int q = 0; q < 32; q++) {
                float2 v = __bfloat1622float2(
                    *reinterpret_cast<const __nv_bfloat162*>(&row[q]));
                s += v.x * v.x + v.y * v.y;
            }
            s_g[r] = s;
        }
        __syncthreads();

        if (tid < NT_) {
            float s = 0.f;
#pragma unroll
            for (int k = 0; k < KP; k++) s += s_g[tid + k];
            s2s[tid] = s;
        }
        __syncthreads();

        float acc[MBW][4][4];
#pragma unroll
        for (int mt = 0; mt < MBW; mt++)
#pragma unroll
            for (int nt = 0; nt < 4; nt++)
#pragma unroll
                for (int e = 0; e < 4; e++) acc[mt][nt][e] = 0.f;

#pragma unroll
        for (int kk = 0; kk < 16; kk++) {
            const uint32_t abase = sp_u32 + kk * SP_TAPB + a_off;
            const uint32_t bbase = sf_u32 + kk * ROWB + b_off;
#pragma unroll
            for (int cc = 0; cc < 4; cc++) {
                uint32_t a[MBW][4], bf[4][2];
#pragma unroll
                for (int mb = 0; mb < MBW; mb++)
                    LDSM4(a[mb][0], a[mb][1], a[mb][2], a[mb][3],
                          abase + mb * (16 * ROWB) + cc * 32);
#pragma unroll
                for (int np = 0; np < 2; np++)
                    LDSM4(bf[2*np][0], bf[2*np][1], bf[2*np+1][0], bf[2*np+1][1],
                          bbase + np * (16 * ROWB) + cc * 32);
#pragma unroll
                for (int mt = 0; mt < MBW; mt++)
#pragma unroll
                    for (int nt = 0; nt < 4; nt++)
                        mma16816(acc[mt][nt], a[mt], bf[nt]);
            }
        }

        // ---- epilogue: dist = relu(s2 - 2*xp + p2), min over t ----
#pragma unroll
        for (int mt = 0; mt < MBW; mt++) {
#pragma unroll
            for (int half = 0; half < 2; half++) {
                const int pl = mt * 16 + g + half * 8;
                const float pp = s_p2[pl];
                float mn = __int_as_float(0x7f800000);
#pragma unroll
                for (int nt = 0; nt < 4; nt++) {
#pragma unroll
                    for (int e = 0; e < 2; e++) {
                        const int col = wid * 32 + nt * 8 + tig * 2 + e;
                        if (t0 + col < LO) {
                            float xp = acc[mt][nt][half * 2 + e];
                            float dd = fmaxf(s2s[col] - 2.f * xp + pp, 0.f);
                            mn = fminf(mn, dd);
                        }
                    }
                }
                atomicMin(&s_md[pl], __float_as_uint(mn));
            }
        }
        __syncthreads();   // sf reuse next iter; s_md complete before write
    }

    if (tid < MB16 && P0 + tid < P_)
        atomicMin(&md[b * P_ + P0 + tid], s_md[tid]);
}

__global__ void __launch_bounds__(256, 1)
gemm_min_kernel(unsigned* __restrict__ md)
{
    extern __shared__ char dynsm[];
    __shared__ float    s_g[FROWS];
    __shared__ float    s2s[NT_];
    __shared__ float    s_p2[128];
    __shared__ unsigned s_md[128];

    if (blockIdx.z == 0)
        gemm_body<5, 0>(md, dynsm, s_g, s2s, s_p2, s_md);
    else if (blockIdx.z == 1)
        gemm_body<5, 80>(md, dynsm, s_g, s2s, s_p2, s_md);
    else
        gemm_body<3, 160>(md, dynsm, s_g, s2s, s_p2, s_md);
}

// ---------------------------------------------------------------------------
// Kernel C: head — one block per batch, warp per class
// ---------------------------------------------------------------------------
__global__ void head_kernel(const float* __restrict__ lw,
                            float* __restrict__ out)
{
    __shared__ float acts[P_];
    const int b   = blockIdx.x;
    const int tid = threadIdx.x;     // 320
    const unsigned* mdb = (const unsigned*)(out + B_ * C_) + b * P_;

    if (tid < P_) {
        float m = __uint_as_float(mdb[tid]);
        acts[tid] = logf((m + 1.0f) / (m + EPS_));
    }
    __syncthreads();

    const int c    = tid >> 5;
    const int lane = tid & 31;
    float s = 0.f;
    for (int p = lane; p < P_; p += 32)
        s += acts[p] * lw[c * P_ + p];
#pragma unroll
    for (int o = 16; o; o >>= 1) s += __shfl_xor_sync(0xffffffffu, s, o);
    if (lane == 0) out[b * C_ + c] = s;
}

// ---------------------------------------------------------------------------
extern "C" void kernel_launch(void* const* d_in, const int* in_sizes, int n_in,
                              void* d_out, int out_size)
{
    const float* x       = (const float*)d_in[0];
    const float* enc_w   = (const float*)d_in[1];
    const float* addon_w = (const float*)d_in[2];
    const float* protos  = (const float*)d_in[3];
    const float* last_w  = (const float*)d_in[4];
    float* out = (float*)d_out;

    cudaFuncSetAttribute(enc_prep_kernel,
                         cudaFuncAttributeMaxDynamicSharedMemorySize, ENC_DYN);
    cudaFuncSetAttribute(gemm_min_kernel,
                         cudaFuncAttributeMaxDynamicSharedMemorySize, GEMM_DYN);

    unsigned* md = (unsigned*)(out + B_ * C_);

    enc_prep_kernel<<<dim3(ENC_XBLKS + PREP_XBLKS, B_), 256, ENC_DYN>>>(
        x, enc_w, addon_w, protos, md);
    gemm_min_kernel<<<dim3(8, B_, 3), 256, GEMM_DYN>>>(md);
    head_kernel<<<B_, 320>>>(last_w, out);
}

// round 17
// speedup vs baseline: 1.0172x; 1.0172x over previous
#include <cuda_runtime.h>
#include <cuda_bf16.h>
#include <cstdint>

// ---------------------------------------------------------------------------
// ProtoTSNet on GB300 — round 17 (best-measured composition)
//  - gemm: R14 exact (grid 16xBx3, 2 t-tiles/CTA, all taps resident,
//    s_g loaded from d_g)
//  - enc: R14 (computes d_g) + w1 staged through smem via cp.async (R16 win)
//
// out[0..319]    = logits [32,10]
// out[320..6719] = min_distances [32,200]
// ---------------------------------------------------------------------------

#define B_     32
#define FIN    16
#define L_     8192
#define LAT    64
#define L1_    8190
#define P_     200
#define KP     16
#define LO     8175
#define C_     10
#define EPS_   1e-4f
#define TPAD   8224

// ---------------- static device scratch (allocation-free) -----------------
__device__ __nv_bfloat16 d_fT[B_ * TPAD * LAT];    // f [b][t][c], bf16
__device__ float         d_g [B_ * TPAD];          // sum_c f_bf16^2
__device__ __nv_bfloat16 d_protA[16 * 256 * LAT];  // protos [kk][p pad256][c]
__device__ float         d_p2[256];                // ||p||^2 (bf16-rounded)

__device__ __forceinline__ uint32_t smem_u32(const void* p) {
    uint32_t a;
    asm("{ .reg .u64 t; cvta.to.shared.u64 t, %1; cvt.u32.u64 %0, t; }"
        : "=r"(a) : "l"(p));
    return a;
}
__device__ __forceinline__ void cp16(uint32_t s, const void* g) {
    asm volatile("cp.async.cg.shared.global [%0], [%1], 16;" :: "r"(s), "l"(g));
}
#define CP_COMMIT() asm volatile("cp.async.commit_group;" ::: "memory")
#define CP_WAIT0()  asm volatile("cp.async.wait_group 0;" ::: "memory")

__device__ __forceinline__ void mma16816(float* c, const uint32_t* a,
                                         const uint32_t* b)
{
    asm volatile(
        "mma.sync.aligned.m16n8k16.row.col.f32.bf16.bf16.f32 "
        "{%0,%1,%2,%3}, {%4,%5,%6,%7}, {%8,%9}, {%0,%1,%2,%3};"
        : "+f"(c[0]), "+f"(c[1]), "+f"(c[2]), "+f"(c[3])
        : "r"(a[0]), "r"(a[1]), "r"(a[2]), "r"(a[3]), "r"(b[0]), "r"(b[1]));
}
#define LDSM4(r0, r1, r2, r3, addr)                                           \
    asm volatile("ldmatrix.sync.aligned.m8n8.x4.shared.b16 {%0,%1,%2,%3},[%4];" \
        : "=r"(r0), "=r"(r1), "=r"(r2), "=r"(r3) : "r"(addr))

__device__ __forceinline__ uint32_t pack_bf2(__nv_bfloat16 a, __nv_bfloat16 b)
{
    return (uint32_t)__bfloat16_as_ushort(a)
         | ((uint32_t)__bfloat16_as_ushort(b) << 16);
}

// ---------------------------------------------------------------------------
// Kernel A: enc (grid.x < 64) + prep (grid.x >= 64), block-range dispatch
// ---------------------------------------------------------------------------
#define B1_ROWB 80
#define OFF_B1  0                       // x tile  [130][80B] (16hi|16lo)
#define OFF_A1  10560                   // w1      [3][64][80B]
#define OFF_A2  25920                   // w2      [64][272B]
#define OFF_B2  43328                   // f1 tile [128][272B]; w1 staging early
#define ENC_DYN 78144
#define ENC_XBLKS 64
#define PREP_XBLKS 40                   // 40*32 = 1280 >= 1249 prep blocks

__device__ void prep_body(int blk, const float* __restrict__ protos,
                          unsigned* __restrict__ md)
{
    const int tid = threadIdx.x;
    if (blk < 1024) {                              // protA rearrange
        int idx = blk * 256 + tid;
        int c  = idx & 63;
        int pp = (idx >> 6) & 255;
        int kk = idx >> 14;
        float v = (pp < P_) ? protos[pp * (LAT * KP) + c * KP + kk] : 0.f;
        d_protA[idx] = __float2bfloat16(v);
    } else if (blk < 1224) {                       // p2
        const int p = blk - 1024;
        float s = 0.f;
        for (int i = tid; i < LAT * KP; i += 256) {
            float v = __bfloat162float(__float2bfloat16(protos[p * LAT * KP + i]));
            s += v * v;
        }
#pragma unroll
        for (int o = 16; o; o >>= 1) s += __shfl_xor_sync(0xffffffffu, s, o);
        __shared__ float red[8];
        if ((tid & 31) == 0) red[tid >> 5] = s;
        __syncthreads();
        if (tid == 0) {
            float ts = 0.f;
            for (int w = 0; w < 8; w++) ts += red[w];
            d_p2[p] = ts;
        }
    } else if (blk < 1249) {                       // init md
        int i = (blk - 1224) * 256 + tid;
        if (i < B_ * P_) md[i] = 0x7f800000u;
    }
}

__global__ void __launch_bounds__(256, 2)
enc_prep_kernel(const float* __restrict__ x,
                const float* __restrict__ ew,
                const float* __restrict__ aw,
                const float* __restrict__ protos,
                unsigned* __restrict__ md)
{
    if (blockIdx.x >= ENC_XBLKS) {
        prep_body((blockIdx.x - ENC_XBLKS) * B_ + blockIdx.y, protos, md);
        return;
    }

    extern __shared__ char esm[];
    __shared__ float s_g2[128];

    const int b   = blockIdx.y;
    const int t0  = blockIdx.x * 128;
    const int tid = threadIdx.x;
    const int lane = tid & 31;
    const int wid  = tid >> 5;
    const int wm  = wid & 3;
    const int wn  = wid >> 2;
    const int sub = lane >> 3;
    const int lr  = lane & 7;
    const int g   = lane >> 2;
    const int tig = lane & 3;

    const uint32_t b1_u = smem_u32(esm) + OFF_B1;
    const uint32_t a1_u = smem_u32(esm) + OFF_A1;
    const uint32_t a2_u = smem_u32(esm) + OFF_A2;
    const uint32_t b2_u = smem_u32(esm) + OFF_B2;

    // ---- stage raw w1 (3072 floats) into B2 scratch via cp.async ----
    for (int i = tid; i < 768; i += 256)
        cp16(b2_u + i * 16, ew + i * 4);
    CP_COMMIT();

    // ---- x tile: load + split hi/lo, packed u32 stores ----
    for (int idx = tid; idx < 8 * 130; idx += 256) {
        int i2 = idx / 130, r = idx - i2 * 130;
        int t = t0 + r;
        int i = i2 * 2;
        float v0 = (t < L_) ? x[(b * FIN + i)     * L_ + t] : 0.f;
        float v1 = (t < L_) ? x[(b * FIN + i + 1) * L_ + t] : 0.f;
        __nv_bfloat16 h0 = __float2bfloat16(v0);
        __nv_bfloat16 h1 = __float2bfloat16(v1);
        __nv_bfloat16 l0 = __float2bfloat16(v0 - __bfloat162float(h0));
        __nv_bfloat16 l1 = __float2bfloat16(v1 - __bfloat162float(h1));
        char* row = esm + OFF_B1 + r * B1_ROWB;
        *reinterpret_cast<uint32_t*>(row + i2 * 4)      = pack_bf2(h0, h1);
        *reinterpret_cast<uint32_t*>(row + 32 + i2 * 4) = pack_bf2(l0, l1);
    }
    // ---- w2: split on the fly (coalesced global), packed ----
    for (int idx = tid; idx < 64 * 32; idx += 256) {
        int c2 = idx & 31, ch2 = idx >> 5;
        float w0 = aw[ch2 * 64 + c2 * 2];
        float w1 = aw[ch2 * 64 + c2 * 2 + 1];
        __nv_bfloat16 h0 = __float2bfloat16(w0);
        __nv_bfloat16 h1 = __float2bfloat16(w1);
        __nv_bfloat16 l0 = __float2bfloat16(w0 - __bfloat162float(h0));
        __nv_bfloat16 l1 = __float2bfloat16(w1 - __bfloat162float(h1));
        char* row = esm + OFF_A2 + ch2 * 272;
        *reinterpret_cast<uint32_t*>(row + c2 * 4)       = pack_bf2(h0, h1);
        *reinterpret_cast<uint32_t*>(row + 128 + c2 * 4) = pack_bf2(l0, l1);
    }
    if (tid < 128) s_g2[tid] = 0.f;

    // ---- w1: split from smem staging ----
    CP_WAIT0();
    __syncthreads();
    const float* ws = reinterpret_cast<const float*>(esm + OFF_B2);
    for (int idx = tid; idx < 3 * 64 * 8; idx += 256) {
        int i2 = idx & 7, ch = (idx >> 3) & 63, tap = idx >> 9;
        int i = i2 * 2;
        float w0 = ws[ch * 48 + i * 3 + tap];
        float w1 = ws[ch * 48 + (i + 1) * 3 + tap];
        __nv_bfloat16 h0 = __float2bfloat16(w0);
        __nv_bfloat16 h1 = __float2bfloat16(w1);
        __nv_bfloat16 l0 = __float2bfloat16(w0 - __bfloat162float(h0));
        __nv_bfloat16 l1 = __float2bfloat16(w1 - __bfloat162float(h1));
        char* row = esm + OFF_A1 + tap * (64 * B1_ROWB) + ch * B1_ROWB;
        *reinterpret_cast<uint32_t*>(row + i2 * 4)      = pack_bf2(h0, h1);
        *reinterpret_cast<uint32_t*>(row + 32 + i2 * 4) = pack_bf2(l0, l1);
    }
    __syncthreads();

    // ---- stage 1: conv k=3 ----
    float acc1[2][4][4];
#pragma unroll
    for (int mt = 0; mt < 2; mt++)
#pragma unroll
        for (int nt = 0; nt < 4; nt++)
#pragma unroll
            for (int e = 0; e < 4; e++) acc1[mt][nt][e] = 0.f;

    const uint32_t a1row  = (uint32_t)(wm * 32 + (sub & 1) * 8 + lr);
    const uint32_t a1colq = (uint32_t)((sub >> 1) * 16);
    const uint32_t w1row  = (uint32_t)((wn * 32 + (sub >> 1) * 8 + lr) * B1_ROWB
                                       + (sub & 1) * 16);

#pragma unroll
    for (int tap = 0; tap < 3; tap++) {
#pragma unroll
        for (int pass = 0; pass < 3; pass++) {
            const uint32_t colA = (pass == 2) ? 32u : 0u;
            const uint32_t colB = (pass == 1) ? 32u : 0u;
            uint32_t bf[4][2];
            const uint32_t wb = a1_u + tap * (64 * B1_ROWB) + w1row + colB;
            LDSM4(bf[0][0], bf[0][1], bf[1][0], bf[1][1], wb);
            LDSM4(bf[2][0], bf[2][1], bf[3][0], bf[3][1], wb + 16 * B1_ROWB);
#pragma unroll
            for (int mt = 0; mt < 2; mt++) {
                uint32_t a[4];
                LDSM4(a[0], a[1], a[2], a[3],
                      b1_u + (a1row + mt * 16 + tap) * B1_ROWB + a1colq + colA);
#pragma unroll
                for (int nt = 0; nt < 4; nt++)
                    mma16816(acc1[mt][nt], a, bf[nt]);
            }
        }
    }
    __syncthreads();   // staging reads done before epilogue 1 overwrites B2

    // ---- epilogue 1 ----
#pragma unroll
    for (int mt = 0; mt < 2; mt++) {
#pragma unroll
        for (int nt = 0; nt < 4; nt++) {
#pragma unroll
            for (int eh = 0; eh < 2; eh++) {
                const int t  = wm * 32 + mt * 16 + g + eh * 8;
                const int ch = wn * 32 + nt * 8 + tig * 2;
                float v0 = fmaxf(acc1[mt][nt][eh * 2 + 0], 0.f);
                float v1 = fmaxf(acc1[mt][nt][eh * 2 + 1], 0.f);
                __nv_bfloat16 h0 = __float2bfloat16(v0);
                __nv_bfloat16 h1 = __float2bfloat16(v1);
                __nv_bfloat16 l0 = __float2bfloat16(v0 - __bfloat162float(h0));
                __nv_bfloat16 l1 = __float2bfloat16(v1 - __bfloat162float(h1));
                char* row = esm + OFF_B2 + t * 272;
                *reinterpret_cast<uint32_t*>(row + ch * 2)       = pack_bf2(h0, h1);
                *reinterpret_cast<uint32_t*>(row + 128 + ch * 2) = pack_bf2(l0, l1);
            }
        }
    }
    __syncthreads();

    // ---- stage 2: 1x1 addon ----
    float acc2[2][4][4];
#pragma unroll
    for (int mt = 0; mt < 2; mt++)
#pragma unroll
        for (int nt = 0; nt < 4; nt++)
#pragma unroll
            for (int e = 0; e < 4; e++) acc2[mt][nt][e] = 0.f;

    const uint32_t a2base = b2_u + (uint32_t)((wm * 32 + (sub & 1) * 8 + lr) * 272
                                              + (sub >> 1) * 16);
    const uint32_t w2base = a2_u + (uint32_t)((wn * 32 + (sub >> 1) * 8 + lr) * 272
                                              + (sub & 1) * 16);

#pragma unroll
    for (int step = 0; step < 12; step++) {
        const int kc   = step & 3;
        const int pass = step >> 2;
        const uint32_t colA = (pass == 2) ? (128u + kc * 32u) : (kc * 32u);
        const uint32_t colB = (pass == 1) ? (128u + kc * 32u) : (kc * 32u);
        uint32_t bf[4][2];
        LDSM4(bf[0][0], bf[0][1], bf[1][0], bf[1][1], w2base + colB);
        LDSM4(bf[2][0], bf[2][1], bf[3][0], bf[3][1], w2base + colB + 16 * 272);
#pragma unroll
        for (int mt = 0; mt < 2; mt++) {
            uint32_t a[4];
            LDSM4(a[0], a[1], a[2], a[3], a2base + mt * (16 * 272) + colA);
#pragma unroll
            for (int nt = 0; nt < 4; nt++)
                mma16816(acc2[mt][nt], a, bf[nt]);
        }
    }

    // ---- epilogue 2: relu, round bf16, store f, accumulate g ----
#pragma unroll
    for (int mt = 0; mt < 2; mt++) {
#pragma unroll
        for (int eh = 0; eh < 2; eh++) {
            const int t  = wm * 32 + mt * 16 + g + eh * 8;
            const int tg = t0 + t;
            float gp = 0.f;
#pragma unroll
            for (int nt = 0; nt < 4; nt++) {
                const int ch = wn * 32 + nt * 8 + tig * 2;
                float v0 = fmaxf(acc2[mt][nt][eh * 2 + 0], 0.f);
                float v1 = fmaxf(acc2[mt][nt][eh * 2 + 1], 0.f);
                __nv_bfloat162 h2 = __floats2bfloat162_rn(v0, v1);
                float r0 = __bfloat162float(__low2bfloat16(h2));
                float r1 = __bfloat162float(__high2bfloat16(h2));
                gp += r0 * r0 + r1 * r1;
                if (tg < L1_)
                    *reinterpret_cast<uint32_t*>(
                        d_fT + ((size_t)b * TPAD + tg) * LAT + ch) =
                        *reinterpret_cast<uint32_t*>(&h2);
            }
            atomicAdd(&s_g2[t], gp);
        }
    }
    __syncthreads();
    if (tid < 128 && t0 + tid < L1_) d_g[b * TPAD + t0 + tid] = s_g2[tid];
}

// ---------------------------------------------------------------------------
// Kernel B: HMMA GEMM + distance + min-reduce (R14 exact)
//   grid (16, B, 3): z chunks 80/80/48 rows, ALL 16 taps resident,
//   2 t-tiles of 256 per CTA, s_g loaded from d_g.
// ---------------------------------------------------------------------------
#define NT_       256
#define FROWS     272
#define ROWB      144
#define SF_BYTES  (FROWS * ROWB)               // 39168
#define GEMM_DYN  (SF_BYTES + 16 * 80 * ROWB)  // 223488

template<int MBW, int P0>
__device__ __forceinline__ void gemm_body(unsigned* __restrict__ md,
                                          char* dynsm, float* s_g, float* s2s,
                                          float* s_p2, unsigned* s_md)
{
    constexpr int MB16 = MBW * 16;
    constexpr int SP_TAPB = MB16 * ROWB;

    char* sf = dynsm;
    char* sp = dynsm + SF_BYTES;

    const int b   = blockIdx.y;
    const int tid = threadIdx.x;
    const int lane = tid & 31;
    const int wid  = tid >> 5;
    const int sub = lane >> 3;
    const int lr  = lane & 7;
    const int g   = lane >> 2;
    const int tig = lane & 3;

    const uint32_t sf_u32 = smem_u32(sf);
    const uint32_t sp_u32 = smem_u32(sp);

    // ---- protos: all 16 taps, loaded once ----
    for (int i = tid; i < 16 * MB16 * 8; i += 256) {
        int j = i / (MB16 * 8), rs = i % (MB16 * 8);
        int r = rs >> 3, seg = rs & 7;
        cp16(sp_u32 + j * SP_TAPB + r * ROWB + seg * 16,
             d_protA + ((size_t)(j * 256 + P0 + r)) * LAT + seg * 8);
    }
    if (tid < 128) {
        s_p2[tid] = d_p2[P0 + tid];
        s_md[tid] = 0x7f800000u;
    }

    const __nv_bfloat16* fT = d_fT + (size_t)b * TPAD * LAT;
    const uint32_t a_off = (uint32_t)(((sub & 1) * 8 + lr) * ROWB
                                      + (sub >> 1) * 16);
    const uint32_t b_off = (uint32_t)((wid * 32 + (sub >> 1) * 8 + lr) * ROWB
                                      + (sub & 1) * 16);

#pragma unroll 1
    for (int it = 0; it < 2; it++) {
        const int t0 = (blockIdx.x * 2 + it) * NT_;

        // f tile for this t-tile (protos stay resident)
        for (int i = tid; i < FROWS * 8; i += 256) {
            int r = i >> 3, seg = i & 7;
            cp16(sf_u32 + r * ROWB + seg * 16,
                 fT + (size_t)(t0 + r) * LAT + seg * 8);
        }
        CP_COMMIT();
        for (int i = tid; i < FROWS; i += 256) s_g[i] = d_g[b * TPAD + t0 + i];
        CP_WAIT0();
        __syncthreads();

        if (tid < NT_) {
            float s = 0.f;
#pragma unroll
            for (int k = 0; k < KP; k++) s += s_g[tid + k];
            s2s[tid] = s;
        }
        __syncthreads();

        float acc[MBW][4][4];
#pragma unroll
        for (int mt = 0; mt < MBW; mt++)
#pragma unroll
            for (int nt = 0; nt < 4; nt++)
#pragma unroll
                for (int e = 0; e < 4; e++) acc[mt][nt][e] = 0.f;

#pragma unroll
        for (int kk = 0; kk < 16; kk++) {
            const uint32_t abase = sp_u32 + kk * SP_TAPB + a_off;
            const uint32_t bbase = sf_u32 + kk * ROWB + b_off;
#pragma unroll
            for (int cc = 0; cc < 4; cc++) {
                uint32_t a[MBW][4], bf[4][2];
#pragma unroll
                for (int mb = 0; mb < MBW; mb++)
                    LDSM4(a[mb][0], a[mb][1], a[mb][2], a[mb][3],
                          abase + mb * (16 * ROWB) + cc * 32);
#pragma unroll
                for (int np = 0; np < 2; np++)
                    LDSM4(bf[2*np][0], bf[2*np][1], bf[2*np+1][0], bf[2*np+1][1],
                          bbase + np * (16 * ROWB) + cc * 32);
#pragma unroll
                for (int mt = 0; mt < MBW; mt++)
#pragma unroll
                    for (int nt = 0; nt < 4; nt++)
                        mma16816(acc[mt][nt], a[mt], bf[nt]);
            }
        }

        // ---- epilogue: dist = relu(s2 - 2*xp + p2), min over t ----
#pragma unroll
        for (int mt = 0; mt < MBW; mt++) {
#pragma unroll
            for (int half = 0; half < 2; half++) {
                const int pl = mt * 16 + g + half * 8;
                const float pp = s_p2[pl];
                float mn = __int_as_float(0x7f800000);
#pragma unroll
                for (int nt = 0; nt < 4; nt++) {
#pragma unroll
                    for (int e = 0; e < 2; e++) {
                        const int col = wid * 32 + nt * 8 + tig * 2 + e;
                        if (t0 + col < LO) {
                            float xp = acc[mt][nt][half * 2 + e];
                            float dd = fmaxf(s2s[col] - 2.f * xp + pp, 0.f);
                            mn = fminf(mn, dd);
                        }
                    }
                }
                atomicMin(&s_md[pl], __float_as_uint(mn));
            }
        }
        __syncthreads();   // sf/s_g reuse next iter; s_md complete before write
    }

    if (tid < MB16 && P0 + tid < P_)
        atomicMin(&md[b * P_ + P0 + tid], s_md[tid]);
}

__global__ void __launch_bounds__(256, 1)
gemm_min_kernel(unsigned* __restrict__ md)
{
    extern __shared__ char dynsm[];
    __shared__ float    s_g[FROWS];
    __shared__ float    s2s[NT_];
    __shared__ float    s_p2[128];
    __shared__ unsigned s_md[128];

    if (blockIdx.z == 0)
        gemm_body<5, 0>(md, dynsm, s_g, s2s, s_p2, s_md);
    else if (blockIdx.z == 1)
        gemm_body<5, 80>(md, dynsm, s_g, s2s, s_p2, s_md);
    else
        gemm_body<3, 160>(md, dynsm, s_g, s2s, s_p2, s_md);
}

// ---------------------------------------------------------------------------
// Kernel C: head — one block per batch, warp per class
// ---------------------------------------------------------------------------
__global__ void head_kernel(const float* __restrict__ lw,
                            float* __restrict__ out)
{
    __shared__ float acts[P_];
    const int b   = blockIdx.x;
    const int tid = threadIdx.x;     // 320
    const unsigned* mdb = (const unsigned*)(out + B_ * C_) + b * P_;

    if (tid < P_) {
        float m = __uint_as_float(mdb[tid]);
        acts[tid] = logf((m + 1.0f) / (m + EPS_));
    }
    __syncthreads();

    const int c    = tid >> 5;
    const int lane = tid & 31;
    float s = 0.f;
    for (int p = lane; p < P_; p += 32)
        s += acts[p] * lw[c * P_ + p];
#pragma unroll
    for (int o = 16; o; o >>= 1) s += __shfl_xor_sync(0xffffffffu, s, o);
    if (lane == 0) out[b * C_ + c] = s;
}

// ---------------------------------------------------------------------------
extern "C" void kernel_launch(void* const* d_in, const int* in_sizes, int n_in,
                              void* d_out, int out_size)
{
    const float* x       = (const float*)d_in[0];
    const float* enc_w   = (const float*)d_in[1];
    const float* addon_w = (const float*)d_in[2];
    const float* protos  = (const float*)d_in[3];
    const float* last_w  = (const float*)d_in[4];
    float* out = (float*)d_out;

    cudaFuncSetAttribute(enc_prep_kernel,
                         cudaFuncAttributeMaxDynamicSharedMemorySize, ENC_DYN);
    cudaFuncSetAttribute(gemm_min_kernel,
                         cudaFuncAttributeMaxDynamicSharedMemorySize, GEMM_DYN);

    unsigned* md = (unsigned*)(out + B_ * C_);

    enc_prep_kernel<<<dim3(ENC_XBLKS + PREP_XBLKS, B_), 256, ENC_DYN>>>(
        x, enc_w, addon_w, protos, md);
    gemm_min_kernel<<<dim3(16, B_, 3), 256, GEMM_DYN>>>(md);
    head_kernel<<<B_, 320>>>(last_w, out);
}